// round 2
// baseline (speedup 1.0000x reference)
#include <cuda_runtime.h>

#define BZ 32
#define TT 1024
#define DD 1024
#define KK 8
#define EE 400

// Scratch (static device globals: no allocation APIs).
__device__ float g_temp[BZ * KK * DD];   // [B, K, D]  = 1 MB
__device__ int   g_seg [BZ * TT];        // span id per token, or -1

// ---------------------------------------------------------------------------
// Kernel 1: per-batch span-id scan.
// span_id = inclusive_cumsum(is_B) - 1 ; valid = (is_B|is_I) && span_id >= 0
// One block per batch, 1024 threads, warp-shfl scan + hierarchical combine.
// ---------------------------------------------------------------------------
__global__ void __launch_bounds__(1024) seg_kernel(
    const int* __restrict__ labels,
    const int* __restrict__ pB,
    const int* __restrict__ pI)
{
    const int b = blockIdx.x;
    const int t = threadIdx.x;
    const int Bi = pB ? *pB : 1;
    const int Ii = pI ? *pI : 2;

    const int lab = labels[b * TT + t];
    const int isB = (lab == Bi) ? 1 : 0;
    const int isI = (lab == Ii) ? 1 : 0;

    const int lane = t & 31;
    const int w    = t >> 5;

    // warp inclusive scan
    int v = isB;
    #pragma unroll
    for (int o = 1; o < 32; o <<= 1) {
        int u = __shfl_up_sync(0xFFFFFFFFu, v, o);
        if (lane >= o) v += u;
    }

    __shared__ int wsum[32];
    if (lane == 31) wsum[w] = v;
    __syncthreads();
    if (w == 0) {
        int x = wsum[lane];
        #pragma unroll
        for (int o = 1; o < 32; o <<= 1) {
            int u = __shfl_up_sync(0xFFFFFFFFu, x, o);
            if (lane >= o) x += u;
        }
        wsum[lane] = x;
    }
    __syncthreads();

    const int incl = v + (w > 0 ? wsum[w - 1] : 0);
    const int span = incl - 1;
    g_seg[b * TT + t] = ((isB | isI) && span >= 0) ? span : -1;
}

// ---------------------------------------------------------------------------
// Kernel 2: temp[b,k,d] = sum_e S[b,e,k] * W[e,d]
// Grid (D/128, B), 128 threads; thread owns one d. S row (8 floats = 2 float4)
// broadcast-read from shared each e. W (1.6 MB) stays L2-resident across the
// 32 batch replays -> FMA-pipe bound, ~5-6 us.
// ---------------------------------------------------------------------------
__global__ void __launch_bounds__(128) temp_kernel(
    const float* __restrict__ S,    // [B, E, K]
    const float* __restrict__ W)    // [E, D]
{
    const int b = blockIdx.y;
    const int d = blockIdx.x * 128 + threadIdx.x;

    __shared__ float4 S_sh[EE * 2];     // 400 * 8 floats = 12.8 KB
    {
        const float4* src = reinterpret_cast<const float4*>(S + (size_t)b * EE * KK);
        for (int i = threadIdx.x; i < EE * 2; i += 128) S_sh[i] = src[i];
    }
    __syncthreads();

    float acc0 = 0.f, acc1 = 0.f, acc2 = 0.f, acc3 = 0.f;
    float acc4 = 0.f, acc5 = 0.f, acc6 = 0.f, acc7 = 0.f;

    #pragma unroll 4
    for (int e = 0; e < EE; e++) {
        const float w = __ldg(W + (size_t)e * DD + d);
        const float4 s01 = S_sh[e * 2];
        const float4 s23 = S_sh[e * 2 + 1];
        acc0 = fmaf(s01.x, w, acc0);
        acc1 = fmaf(s01.y, w, acc1);
        acc2 = fmaf(s01.z, w, acc2);
        acc3 = fmaf(s01.w, w, acc3);
        acc4 = fmaf(s23.x, w, acc4);
        acc5 = fmaf(s23.y, w, acc5);
        acc6 = fmaf(s23.z, w, acc6);
        acc7 = fmaf(s23.w, w, acc7);
    }

    float* tp = g_temp + ((size_t)b * KK) * DD + d;
    tp[0 * DD] = acc0; tp[1 * DD] = acc1; tp[2 * DD] = acc2; tp[3 * DD] = acc3;
    tp[4 * DD] = acc4; tp[5 * DD] = acc5; tp[6 * DD] = acc6; tp[7 * DD] = acc7;
}

// ---------------------------------------------------------------------------
// Kernel 3 (main, HBM-bound): q[b,t,k] = dot(temp[b,k,:], h[b,t,:]) folded
// directly into the segment sum via atomicAdd.
//
// Block = 128 threads (4 warps), 64 tokens. Warp w owns D-quarter
// [w*256, w*256+256): lane covers 8 floats (two float4s, 512B-coalesced LDG,
// MLP=8 per lane-group). temp for the whole batch row sits in 32 KB shared,
// conflict-free float4 reads amortized over 4-token register groups.
// Per-(tok,k) lane-partials are combined with a 31-shfl butterfly-halving
// all-reduce: flattened value index l = tok*8+k lands fully reduced on lane
// l, which issues one atomicAdd per (token,k) into out[b][span][k].
// ---------------------------------------------------------------------------
__global__ void __launch_bounds__(128) main_kernel(
    const float* __restrict__ hidden,   // [B, T, D]
    float* __restrict__ out)            // [B, T, K], pre-zeroed
{
    const int b    = blockIdx.y;
    const int tok0 = blockIdx.x * 64;
    const int warp = threadIdx.x >> 5;
    const int lane = threadIdx.x & 31;

    __shared__ float tmp_sh[KK * DD];   // 32 KB
    __shared__ int   seg_sh[64];

    {
        const float4* src = reinterpret_cast<const float4*>(g_temp + (size_t)b * KK * DD);
        float4* dst = reinterpret_cast<float4*>(tmp_sh);
        #pragma unroll 4
        for (int i = threadIdx.x; i < KK * DD / 4; i += 128) dst[i] = src[i];
    }
    if (threadIdx.x < 64) seg_sh[threadIdx.x] = g_seg[b * TT + tok0 + threadIdx.x];
    __syncthreads();

    const int qb = warp * 256;           // this warp's D-quarter
    const int d0 = qb + lane * 4;        // first float4
    const int d1 = d0 + 128;             // second float4
    const float* hb = hidden + ((size_t)b * TT + tok0) * DD;

    #pragma unroll 1
    for (int g = 0; g < 64; g += 4) {
        // Load hidden for 4 tokens: 8 independent 512B-coalesced LDG.128/lane.
        float4 h0[4], h1[4];
        #pragma unroll
        for (int t = 0; t < 4; t++) {
            const float* hp = hb + (size_t)(g + t) * DD;
            h0[t] = *reinterpret_cast<const float4*>(hp + d0);
            h1[t] = *reinterpret_cast<const float4*>(hp + d1);
        }

        float v[32];   // v[t*8+k] = this lane's 8-float partial dot
        #pragma unroll
        for (int k = 0; k < KK; k++) {
            const float4 ta = *reinterpret_cast<const float4*>(tmp_sh + k * DD + d0);
            const float4 tb = *reinterpret_cast<const float4*>(tmp_sh + k * DD + d1);
            #pragma unroll
            for (int t = 0; t < 4; t++) {
                float a;
                a = h0[t].x * ta.x;
                a = fmaf(h0[t].y, ta.y, a);
                a = fmaf(h0[t].z, ta.z, a);
                a = fmaf(h0[t].w, ta.w, a);
                a = fmaf(h1[t].x, tb.x, a);
                a = fmaf(h1[t].y, tb.y, a);
                a = fmaf(h1[t].z, tb.z, a);
                a = fmaf(h1[t].w, tb.w, a);
                v[t * 8 + k] = a;
            }
        }

        // Butterfly-halving all-reduce: 32 distinct values x 32 lanes.
        // After step m, the kept half's base index gains (lane & m); the
        // final fully-reduced value index == lane.
        #pragma unroll
        for (int m = 16; m >= 1; m >>= 1) {
            const bool up = (lane & m) != 0;
            #pragma unroll
            for (int i = 0; i < m; i++) {
                float send = up ? v[i] : v[i + m];
                float recv = __shfl_xor_sync(0xFFFFFFFFu, send, m);
                v[i] = (up ? v[i + m] : v[i]) + recv;
            }
        }

        const int t = lane >> 3;      // token within group
        const int k = lane & 7;
        const int s = seg_sh[g + t];
        if (s >= 0)
            atomicAdd(out + ((size_t)b * TT + s) * KK + k, v[0]);
    }
}

// ---------------------------------------------------------------------------
extern "C" void kernel_launch(void* const* d_in, const int* in_sizes, int n_in,
                              void* d_out, int out_size)
{
    const float* hidden = (const float*)d_in[0];   // [32,1024,1024] f32
    const float* slot   = (const float*)d_in[1];   // [32,400,8]     f32
    const float* W      = (const float*)d_in[2];   // [400,1024]     f32
    const int*   labels = (const int*)  d_in[3];   // [32,1024]      i32
    const int*   pB     = (n_in > 4) ? (const int*)d_in[4] : nullptr;
    const int*   pI     = (n_in > 5) ? (const int*)d_in[5] : nullptr;
    float* out = (float*)d_out;

    (void)in_sizes;

    // Output is poisoned 0xAA; segment-sum accumulates, so zero first.
    cudaMemsetAsync(d_out, 0, (size_t)out_size * sizeof(float));

    seg_kernel <<<BZ, 1024>>>(labels, pB, pI);
    temp_kernel<<<dim3(DD / 128, BZ), 128>>>(slot, W);
    main_kernel<<<dim3(TT / 64,  BZ), 128>>>(hidden, out);
}

// round 3
// speedup vs baseline: 2.0462x; 2.0462x over previous
#include <cuda_runtime.h>

#define BZ 32
#define TT 1024
#define DD 1024
#define KK 8
#define EE 400
#define ESPLIT 4
#define ECHUNK 100   // EE / ESPLIT

// Scratch (static device globals: no allocation APIs).
__device__ float g_temp[BZ * KK * DD];   // [B, K, D] = 1 MB, atomically accumulated
__device__ int   g_seg [BZ * TT];        // span id per token, or -1

// ---------------------------------------------------------------------------
// Kernel 1: span-id scan + zeroing of g_temp and out.
// One block per batch, 1024 threads. 32K threads zero 2 x 1MB (8 floats each
// per buffer) -- replaces the separate cudaMemsetAsync so the replay is
// exactly 3 launches (=> ncu -s 5 -c 1 profiles main_kernel).
// ---------------------------------------------------------------------------
__global__ void __launch_bounds__(1024) seg_kernel(
    const int* __restrict__ labels,
    const int* __restrict__ pB,
    const int* __restrict__ pI,
    float* __restrict__ out)
{
    const int b = blockIdx.x;
    const int t = threadIdx.x;
    const int gid = b * TT + t;

    // Zero g_temp (atomic accumulator) and out (segment-sum accumulator).
    {
        const float4 z = make_float4(0.f, 0.f, 0.f, 0.f);
        float4* tp = reinterpret_cast<float4*>(g_temp) + gid * 2;
        tp[0] = z; tp[1] = z;
        float4* op = reinterpret_cast<float4*>(out) + gid * 2;
        op[0] = z; op[1] = z;
    }

    const int Bi = pB ? *pB : 1;
    const int Ii = pI ? *pI : 2;

    const int lab = labels[gid];
    const int isB = (lab == Bi) ? 1 : 0;
    const int isI = (lab == Ii) ? 1 : 0;

    const int lane = t & 31;
    const int w    = t >> 5;

    // warp inclusive scan of isB
    int v = isB;
    #pragma unroll
    for (int o = 1; o < 32; o <<= 1) {
        int u = __shfl_up_sync(0xFFFFFFFFu, v, o);
        if (lane >= o) v += u;
    }

    __shared__ int wsum[32];
    if (lane == 31) wsum[w] = v;
    __syncthreads();
    if (w == 0) {
        int x = wsum[lane];
        #pragma unroll
        for (int o = 1; o < 32; o <<= 1) {
            int u = __shfl_up_sync(0xFFFFFFFFu, x, o);
            if (lane >= o) x += u;
        }
        wsum[lane] = x;
    }
    __syncthreads();

    const int incl = v + (w > 0 ? wsum[w - 1] : 0);
    const int span = incl - 1;
    g_seg[gid] = ((isB | isI) && span >= 0) ? span : -1;
}

// ---------------------------------------------------------------------------
// Kernel 2: temp[b,k,d] += sum_{e in chunk} S[b,e,k] * W[e,d]
// Grid (D/128, B, ESPLIT) = 1024 blocks -> ~7 blocks/SM (was 1.7: the old
// version was latency-exposed at 256 blocks). Partials merged via atomicAdd
// (g_temp zeroed by seg_kernel; stream order guarantees visibility).
// ---------------------------------------------------------------------------
__global__ void __launch_bounds__(128) temp_kernel(
    const float* __restrict__ S,    // [B, E, K]
    const float* __restrict__ W)    // [E, D]
{
    const int b  = blockIdx.y;
    const int d  = blockIdx.x * 128 + threadIdx.x;
    const int e0 = blockIdx.z * ECHUNK;

    __shared__ float4 S_sh[ECHUNK * 2];   // 100 e-rows x 8 floats
    {
        const float4* src = reinterpret_cast<const float4*>(
            S + (size_t)b * EE * KK + (size_t)e0 * KK);
        for (int i = threadIdx.x; i < ECHUNK * 2; i += 128) S_sh[i] = src[i];
    }
    __syncthreads();

    float a0 = 0.f, a1 = 0.f, a2 = 0.f, a3 = 0.f;
    float a4 = 0.f, a5 = 0.f, a6 = 0.f, a7 = 0.f;

    #pragma unroll 10
    for (int e = 0; e < ECHUNK; e++) {
        const float w = __ldg(W + (size_t)(e0 + e) * DD + d);
        const float4 s01 = S_sh[e * 2];
        const float4 s23 = S_sh[e * 2 + 1];
        a0 = fmaf(s01.x, w, a0);
        a1 = fmaf(s01.y, w, a1);
        a2 = fmaf(s01.z, w, a2);
        a3 = fmaf(s01.w, w, a3);
        a4 = fmaf(s23.x, w, a4);
        a5 = fmaf(s23.y, w, a5);
        a6 = fmaf(s23.z, w, a6);
        a7 = fmaf(s23.w, w, a7);
    }

    float* tp = g_temp + (size_t)b * KK * DD + d;
    atomicAdd(tp + 0 * DD, a0);
    atomicAdd(tp + 1 * DD, a1);
    atomicAdd(tp + 2 * DD, a2);
    atomicAdd(tp + 3 * DD, a3);
    atomicAdd(tp + 4 * DD, a4);
    atomicAdd(tp + 5 * DD, a5);
    atomicAdd(tp + 6 * DD, a6);
    atomicAdd(tp + 7 * DD, a7);
}

// ---------------------------------------------------------------------------
// Kernel 3 (main, HBM-bound): q[b,t,k] = dot(temp[b,k,:], h[b,t,:]) folded
// into the segment sum via atomicAdd.
//
// Grid (T/64, B, 2), block 128 (4 warps). blockIdx.z picks the D-half; warp
// w owns D-slice [slice*128, slice*128+128): one float4 per lane. The 8 temp
// float4s for the slice live in REGISTERS (loaded once from L2) -- no shared
// temp tile, no in-loop LDS, regs ~95 -> ~20 warps/SM (the old version had
// ~110+ regs + 32KB smem -> <=16 warps and starved DRAM concurrency).
//
// Per 4-token group: 4 x LDG.128 (coalesced 512B), 128 FFMA, then a 31-shfl
// butterfly-halving all-reduce (value l = tok*8+k lands on lane l), then one
// atomicAdd per lane into out[b][span][k]. Atomics merge the 8 D-slice
// partials and the cross-warp/cross-block span pieces.
// ---------------------------------------------------------------------------
__global__ void __launch_bounds__(128) main_kernel(
    const float* __restrict__ hidden,   // [B, T, D]
    float* __restrict__ out)            // [B, T, K], pre-zeroed by seg_kernel
{
    const int b     = blockIdx.y;
    const int tok0  = blockIdx.x * 64;
    const int warp  = threadIdx.x >> 5;
    const int lane  = threadIdx.x & 31;
    const int slice = blockIdx.z * 4 + warp;     // 0..7
    const int d0    = slice * 128 + lane * 4;

    __shared__ int seg_sh[64];
    if (threadIdx.x < 64) seg_sh[threadIdx.x] = g_seg[b * TT + tok0 + threadIdx.x];
    __syncthreads();

    // temp slice in registers: 8 float4 = 32 regs, read from L2 once.
    float4 ta[KK];
    #pragma unroll
    for (int k = 0; k < KK; k++)
        ta[k] = *reinterpret_cast<const float4*>(
            g_temp + (size_t)b * KK * DD + (size_t)k * DD + d0);

    const float* hb = hidden + ((size_t)b * TT + tok0) * DD + d0;

    #pragma unroll 1
    for (int g = 0; g < 64; g += 4) {
        // 4 independent coalesced LDG.128 (evict-first: hidden is read once).
        float4 h[4];
        #pragma unroll
        for (int t = 0; t < 4; t++)
            h[t] = __ldcs(reinterpret_cast<const float4*>(hb + (size_t)(g + t) * DD));

        float v[32];   // v[t*8+k] = this lane's 4-float partial dot
        #pragma unroll
        for (int k = 0; k < KK; k++) {
            #pragma unroll
            for (int t = 0; t < 4; t++) {
                float a;
                a = h[t].x * ta[k].x;
                a = fmaf(h[t].y, ta[k].y, a);
                a = fmaf(h[t].z, ta[k].z, a);
                a = fmaf(h[t].w, ta[k].w, a);
                v[t * 8 + k] = a;
            }
        }

        // Butterfly-halving all-reduce: 32 values x 32 lanes; fully-reduced
        // value index == lane after the 5 steps.
        #pragma unroll
        for (int m = 16; m >= 1; m >>= 1) {
            const bool up = (lane & m) != 0;
            #pragma unroll
            for (int i = 0; i < m; i++) {
                float send = up ? v[i] : v[i + m];
                float recv = __shfl_xor_sync(0xFFFFFFFFu, send, m);
                v[i] = (up ? v[i + m] : v[i]) + recv;
            }
        }

        const int s = seg_sh[g + (lane >> 3)];
        if (s >= 0)
            atomicAdd(out + ((size_t)b * TT + s) * KK + (lane & 7), v[0]);
    }
}

// ---------------------------------------------------------------------------
extern "C" void kernel_launch(void* const* d_in, const int* in_sizes, int n_in,
                              void* d_out, int out_size)
{
    const float* hidden = (const float*)d_in[0];   // [32,1024,1024] f32
    const float* slot   = (const float*)d_in[1];   // [32,400,8]     f32
    const float* W      = (const float*)d_in[2];   // [400,1024]     f32
    const int*   labels = (const int*)  d_in[3];   // [32,1024]      i32
    const int*   pB     = (n_in > 4) ? (const int*)d_in[4] : nullptr;
    const int*   pI     = (n_in > 5) ? (const int*)d_in[5] : nullptr;
    float* out = (float*)d_out;

    (void)in_sizes; (void)out_size;

    // Exactly 3 launches per replay (seg zeroes g_temp + out).
    seg_kernel <<<BZ, 1024>>>(labels, pB, pI, out);
    temp_kernel<<<dim3(DD / 128, BZ, ESPLIT), 128>>>(slot, W);
    main_kernel<<<dim3(TT / 64,  BZ, 2),      128>>>(hidden, out);
}

// round 6
// speedup vs baseline: 2.0476x; 1.0007x over previous
#include <cuda_runtime.h>

#define BZ 32
#define TT 1024
#define DD 1024
#define KK 8
#define EE 400
#define ESPLIT 8
#define ECHUNK 50    // EE / ESPLIT

// Scratch (static device globals: no allocation APIs).
__device__ float g_temp4[ESPLIT * BZ * KK * DD];  // 8 MB: per-E-chunk partials (plain stores)
__device__ float g_temp [BZ * KK * DD];           // 1 MB: reduced temp[b][k][d]

// ---------------------------------------------------------------------------
// Kernel 1: temp partials. temp4[z][b][k][d] = sum_{e in chunk z} S[b,e,k]*W[e,d]
// Grid (D/256, B/2, ESPLIT) = 512 blocks, 128 threads; thread owns a d-PAIR
// and computes both batches of its b-pair (halves W L2 traffic). Packed
// fma.rn.f32x2 halves FMA-pipe instruction count; S values stored
// pre-duplicated ((s,s) in 64-bit words) so no packing in the inner loop.
// Plain stores -> no zeroing, no atomics.
// ---------------------------------------------------------------------------
__global__ void __launch_bounds__(128) temp_partial_kernel(
    const float* __restrict__ S,    // [B, E, K]
    const float* __restrict__ W)    // [E, D]
{
    const int tid = threadIdx.x;
    const int b0  = blockIdx.y * 2;
    const int z   = blockIdx.z;
    const int e0  = z * ECHUNK;
    const int d0  = blockIdx.x * 256 + tid * 2;

    __shared__ unsigned long long S_dup[2][ECHUNK * KK];   // 6.4 KB
    for (int i = tid; i < 2 * ECHUNK * KK; i += 128) {
        const int bsel = i / (ECHUNK * KK);
        const int j    = i % (ECHUNK * KK);
        const float s = S[(size_t)(b0 + bsel) * EE * KK + (size_t)e0 * KK + j];
        unsigned long long p;
        asm("mov.b64 %0, {%1, %1};" : "=l"(p) : "f"(s));
        S_dup[bsel][j] = p;
    }
    __syncthreads();

    unsigned long long acc[2][KK];
    #pragma unroll
    for (int b = 0; b < 2; b++)
        #pragma unroll
        for (int k = 0; k < KK; k++) acc[b][k] = 0ULL;   // bits of (0.f, 0.f)

    #pragma unroll 5
    for (int e = 0; e < ECHUNK; e++) {
        const float2 w = *reinterpret_cast<const float2*>(W + (size_t)(e0 + e) * DD + d0);
        unsigned long long w2;
        asm("mov.b64 %0, {%1, %2};" : "=l"(w2) : "f"(w.x), "f"(w.y));
        #pragma unroll
        for (int b = 0; b < 2; b++) {
            const ulonglong2* sp =
                reinterpret_cast<const ulonglong2*>(&S_dup[b][e * KK]);
            #pragma unroll
            for (int k2 = 0; k2 < 4; k2++) {
                const ulonglong2 s2 = sp[k2];   // (s_{2k2},s_{2k2}) , (s_{2k2+1},s_{2k2+1})
                asm("fma.rn.f32x2 %0, %1, %2, %0;" : "+l"(acc[b][2*k2    ]) : "l"(w2), "l"(s2.x));
                asm("fma.rn.f32x2 %0, %1, %2, %0;" : "+l"(acc[b][2*k2 + 1]) : "l"(w2), "l"(s2.y));
            }
        }
    }

    #pragma unroll
    for (int b = 0; b < 2; b++) {
        #pragma unroll
        for (int k = 0; k < KK; k++) {
            float lo, hi;
            asm("mov.b64 {%0, %1}, %2;" : "=f"(lo), "=f"(hi) : "l"(acc[b][k]));
            *reinterpret_cast<float2*>(
                g_temp4 + (((size_t)z * BZ + (b0 + b)) * KK + k) * DD + d0)
                = make_float2(lo, hi);
        }
    }
}

// ---------------------------------------------------------------------------
// Kernel 2: reduce the 8 E-chunk partials into g_temp, and zero `out`.
// 256 blocks x 256 threads = 65536 threads; each thread owns ONE float4 of
// g_temp AND zeroes ONE float4 of out (65536 float4 = 262144 floats = B*T*K,
// the full output).
// ---------------------------------------------------------------------------
__global__ void __launch_bounds__(256) temp_reduce_kernel(float* __restrict__ out)
{
    const int i = blockIdx.x * 256 + threadIdx.x;            // float4 index
    const float4* src = reinterpret_cast<const float4*>(g_temp4);
    float4 a = src[i];
    #pragma unroll
    for (int z = 1; z < ESPLIT; z++) {
        const float4 t = src[(size_t)z * (BZ * KK * DD / 4) + i];
        a.x += t.x; a.y += t.y; a.z += t.z; a.w += t.w;
    }
    reinterpret_cast<float4*>(g_temp)[i] = a;
    reinterpret_cast<float4*>(out)[i] = make_float4(0.f, 0.f, 0.f, 0.f);
}

// ---------------------------------------------------------------------------
// Kernel 3 (main, HBM-bound): q[b,t,k] = dot(temp[b,k,:], h[b,t,:]) folded
// into the segment sum via atomicAdd.
//
// Grid (T/64, B, 2), block 128 (4 warps). Prologue: block re-derives the
// span-id scan from the 1024 labels of its batch (4 KB, L2-hit) -- no
// separate seg launch. Warp owns D-slice [slice*128,+128); the 8 temp
// float4s for the slice live in registers. Per 4-token group: 4 coalesced
// LDG.128 (evict-first), 128 FFMA, then a 31-shfl butterfly-halving
// all-reduce (value l = tok*8+k lands fully reduced on lane l), then one
// atomicAdd per lane into out[b][span][k].
// [NOTE: redux.sync.add.f32 does NOT exist (f32 redux is min/max only) --
//  that invalid PTX is what broke rounds 4-5.]
// ---------------------------------------------------------------------------
__global__ void __launch_bounds__(128) main_kernel(
    const float* __restrict__ hidden,   // [B, T, D]
    const int*   __restrict__ labels,   // [B, T]
    const int*   __restrict__ pB,
    const int*   __restrict__ pI,
    float* __restrict__ out)            // [B, T, K], zeroed by temp_reduce
{
    const int tid   = threadIdx.x;
    const int b     = blockIdx.y;
    const int tok0  = blockIdx.x * 64;
    const int warp  = tid >> 5;
    const int lane  = tid & 31;
    const int slice = blockIdx.z * 4 + warp;     // 0..7
    const int d0    = slice * 128 + lane * 4;

    __shared__ int seg_sh[64];
    __shared__ int wsum[4];

    // ---- in-block span-id scan over all 1024 tokens of batch b ----
    {
        const int Bi = pB ? *pB : 1;
        const int Ii = pI ? *pI : 2;
        const int4* lb = reinterpret_cast<const int4*>(labels + b * TT);
        const int4 pa  = lb[tid * 2];
        const int4 pb4 = lb[tid * 2 + 1];
        int l[8] = {pa.x, pa.y, pa.z, pa.w, pb4.x, pb4.y, pb4.z, pb4.w};

        int cnt = 0;
        #pragma unroll
        for (int j = 0; j < 8; j++) cnt += (l[j] == Bi);

        int incl = cnt;
        #pragma unroll
        for (int o = 1; o < 32; o <<= 1) {
            const int u = __shfl_up_sync(0xFFFFFFFFu, incl, o);
            if (lane >= o) incl += u;
        }
        if (lane == 31) wsum[warp] = incl;
        __syncthreads();

        int base = 0;
        #pragma unroll
        for (int wv = 0; wv < 4; wv++) base += (wv < warp) ? wsum[wv] : 0;

        int run = base + incl - cnt;     // exclusive B-count before token tid*8
        #pragma unroll
        for (int j = 0; j < 8; j++) {
            const int isB = (l[j] == Bi);
            run += isB;
            const int span  = run - 1;
            const bool valid = (isB | (l[j] == Ii)) && span >= 0;
            const int tokg = tid * 8 + j;
            if ((unsigned)(tokg - tok0) < 64u)
                seg_sh[tokg - tok0] = valid ? span : -1;
        }
    }
    __syncthreads();

    // temp slice in registers: 8 float4 = 32 regs, read once from L2.
    float4 ta[KK];
    #pragma unroll
    for (int k = 0; k < KK; k++)
        ta[k] = *reinterpret_cast<const float4*>(
            g_temp + ((size_t)b * KK + k) * DD + d0);

    const float* hb = hidden + ((size_t)b * TT + tok0) * DD + d0;
    float* const ob = out + (size_t)b * TT * KK + (lane & 7);
    const int myt = lane >> 3;

    #pragma unroll 1
    for (int g = 0; g < 64; g += 4) {
        // 4 independent coalesced LDG.128 (evict-first: hidden read once).
        float4 h[4];
        #pragma unroll
        for (int t = 0; t < 4; t++)
            h[t] = __ldcs(reinterpret_cast<const float4*>(hb + (size_t)(g + t) * DD));

        float v[32];   // v[t*8+k] = this lane's 4-float partial dot
        #pragma unroll
        for (int k = 0; k < KK; k++) {
            #pragma unroll
            for (int t = 0; t < 4; t++) {
                float a;
                a = h[t].x * ta[k].x;
                a = fmaf(h[t].y, ta[k].y, a);
                a = fmaf(h[t].z, ta[k].z, a);
                a = fmaf(h[t].w, ta[k].w, a);
                v[t * 8 + k] = a;
            }
        }

        // Butterfly-halving all-reduce: 32 values x 32 lanes; after steps
        // m=16..1, the fully-reduced value index == lane (kept half's base
        // index accumulates (lane & m) each step).
        #pragma unroll
        for (int m = 16; m >= 1; m >>= 1) {
            const bool up = (lane & m) != 0;
            #pragma unroll
            for (int i = 0; i < m; i++) {
                float send = up ? v[i] : v[i + m];
                float recv = __shfl_xor_sync(0xFFFFFFFFu, send, m);
                v[i] = (up ? v[i + m] : v[i]) + recv;
            }
        }

        const int s = seg_sh[g + myt];
        if (s >= 0)
            atomicAdd(ob + (size_t)s * KK, v[0]);
    }
}

// ---------------------------------------------------------------------------
extern "C" void kernel_launch(void* const* d_in, const int* in_sizes, int n_in,
                              void* d_out, int out_size)
{
    const float* hidden = (const float*)d_in[0];   // [32,1024,1024] f32
    const float* slot   = (const float*)d_in[1];   // [32,400,8]     f32
    const float* W      = (const float*)d_in[2];   // [400,1024]     f32
    const int*   labels = (const int*)  d_in[3];   // [32,1024]      i32
    const int*   pB     = (n_in > 4) ? (const int*)d_in[4] : nullptr;
    const int*   pI     = (n_in > 5) ? (const int*)d_in[5] : nullptr;
    float* out = (float*)d_out;

    (void)in_sizes; (void)out_size;

    // Exactly 3 launches per replay (=> ncu -s 5 -c 1 profiles main_kernel).
    temp_partial_kernel<<<dim3(DD / 256, BZ / 2, ESPLIT), 128>>>(slot, W);
    temp_reduce_kernel <<<BZ * KK * DD / 4 / 256, 256>>>(out);
    main_kernel        <<<dim3(TT / 64, BZ, 2), 128>>>(hidden, labels, pB, pI, out);
}

// round 8
// speedup vs baseline: 2.1315x; 1.0410x over previous
#include <cuda_runtime.h>

#define BZ 32
#define TT 1024
#define DD 1024
#define KK 8
#define EE 400
#define ESPLIT 16
#define ECHUNK 25    // EE / ESPLIT

// Scratch (static device globals: no allocation APIs).
__device__ float g_temp4[ESPLIT * BZ * KK * DD];  // 16 MB: per-E-chunk partials
__device__ float g_temp [BZ * KK * DD];           // 1 MB: reduced temp[b][k][d]

// ---------------------------------------------------------------------------
// Kernel 1: temp partials. temp4[z][b][k][d] = sum_{e in chunk z} S[b,e,k]*W[e,d]
// Grid (2, B/2, 16) = 512 blocks, 128 threads.
// Thread owns a d-QUAD (one coalesced LDG.128 of W per e) for a b-PAIR and
// all 8 k -> per e: 1 LDG.128 + 8 broadcast LDS.128 + 32 fma.rn.f32x2
// (78% FMA density; R6 version was 59% and latency-starved at 18% issue).
// S values pre-duplicated ((s,s) in 64-bit words) in shared. Plain stores.
// ---------------------------------------------------------------------------
__global__ void __launch_bounds__(128) temp_partial_kernel(
    const float* __restrict__ S,    // [B, E, K]
    const float* __restrict__ W)    // [E, D]
{
    const int tid = threadIdx.x;
    const int b0  = blockIdx.y * 2;
    const int z   = blockIdx.z;
    const int e0  = z * ECHUNK;
    const int d0  = blockIdx.x * 512 + tid * 4;

    __shared__ unsigned long long S_dup[2][ECHUNK * KK];   // 3.2 KB
    for (int i = tid; i < 2 * ECHUNK * KK; i += 128) {
        const int bsel = i / (ECHUNK * KK);
        const int j    = i % (ECHUNK * KK);
        const float s = S[(size_t)(b0 + bsel) * EE * KK + (size_t)e0 * KK + j];
        unsigned long long p;
        asm("mov.b64 %0, {%1, %1};" : "=l"(p) : "f"(s));
        S_dup[bsel][j] = p;
    }
    __syncthreads();

    // acc[b][k] = (f32x2 lo-pair, f32x2 hi-pair) for this thread's d-quad.
    unsigned long long acc[2][KK][2];
    #pragma unroll
    for (int b = 0; b < 2; b++)
        #pragma unroll
        for (int k = 0; k < KK; k++) { acc[b][k][0] = 0ULL; acc[b][k][1] = 0ULL; }

    #pragma unroll 5
    for (int e = 0; e < ECHUNK; e++) {
        const float4 w = *reinterpret_cast<const float4*>(W + (size_t)(e0 + e) * DD + d0);
        unsigned long long w2a, w2b;
        asm("mov.b64 %0, {%1, %2};" : "=l"(w2a) : "f"(w.x), "f"(w.y));
        asm("mov.b64 %0, {%1, %2};" : "=l"(w2b) : "f"(w.z), "f"(w.w));
        #pragma unroll
        for (int b = 0; b < 2; b++) {
            const ulonglong2* sp =
                reinterpret_cast<const ulonglong2*>(&S_dup[b][e * KK]);
            #pragma unroll
            for (int k2 = 0; k2 < 4; k2++) {
                const ulonglong2 s2 = sp[k2];   // dup-pairs for k=2*k2, 2*k2+1
                asm("fma.rn.f32x2 %0, %1, %2, %0;" : "+l"(acc[b][2*k2  ][0]) : "l"(w2a), "l"(s2.x));
                asm("fma.rn.f32x2 %0, %1, %2, %0;" : "+l"(acc[b][2*k2  ][1]) : "l"(w2b), "l"(s2.x));
                asm("fma.rn.f32x2 %0, %1, %2, %0;" : "+l"(acc[b][2*k2+1][0]) : "l"(w2a), "l"(s2.y));
                asm("fma.rn.f32x2 %0, %1, %2, %0;" : "+l"(acc[b][2*k2+1][1]) : "l"(w2b), "l"(s2.y));
            }
        }
    }

    // Bits of (lo,hi) f32x2 pairs ARE the 4 packed floats: store as 128-bit.
    #pragma unroll
    for (int b = 0; b < 2; b++) {
        #pragma unroll
        for (int k = 0; k < KK; k++) {
            ulonglong2 o; o.x = acc[b][k][0]; o.y = acc[b][k][1];
            *reinterpret_cast<ulonglong2*>(
                g_temp4 + (((size_t)z * BZ + (b0 + b)) * KK + k) * DD + d0) = o;
        }
    }
}

// ---------------------------------------------------------------------------
// Kernel 2: reduce the 16 E-chunk partials into g_temp, and zero `out`.
// 256 blocks x 256 threads = 65536 threads; thread owns ONE float4 of g_temp
// AND zeroes ONE float4 of out (65536*4 = 262144 floats = B*T*K, full output).
// ---------------------------------------------------------------------------
__global__ void __launch_bounds__(256) temp_reduce_kernel(float* __restrict__ out)
{
    const int i = blockIdx.x * 256 + threadIdx.x;            // float4 index
    const float4* src = reinterpret_cast<const float4*>(g_temp4);
    float4 a = src[i];
    #pragma unroll
    for (int z = 1; z < ESPLIT; z++) {
        const float4 t = src[(size_t)z * (BZ * KK * DD / 4) + i];
        a.x += t.x; a.y += t.y; a.z += t.z; a.w += t.w;
    }
    reinterpret_cast<float4*>(g_temp)[i] = a;
    reinterpret_cast<float4*>(out)[i] = make_float4(0.f, 0.f, 0.f, 0.f);
}

// ---------------------------------------------------------------------------
// Kernel 3 (main, HBM-bound): q[b,t,k] = dot(temp[b,k,:], h[b,t,:]) folded
// into the segment sum via atomicAdd. (Unchanged from R6: ~25us, near the
// ~21us DRAM floor; will revisit with profile evidence.)
// ---------------------------------------------------------------------------
__global__ void __launch_bounds__(128) main_kernel(
    const float* __restrict__ hidden,   // [B, T, D]
    const int*   __restrict__ labels,   // [B, T]
    const int*   __restrict__ pB,
    const int*   __restrict__ pI,
    float* __restrict__ out)            // [B, T, K], zeroed by temp_reduce
{
    const int tid   = threadIdx.x;
    const int b     = blockIdx.y;
    const int tok0  = blockIdx.x * 64;
    const int warp  = tid >> 5;
    const int lane  = tid & 31;
    const int slice = blockIdx.z * 4 + warp;     // 0..7
    const int d0    = slice * 128 + lane * 4;

    __shared__ int seg_sh[64];
    __shared__ int wsum[4];

    // ---- in-block span-id scan over all 1024 tokens of batch b ----
    {
        const int Bi = pB ? *pB : 1;
        const int Ii = pI ? *pI : 2;
        const int4* lb = reinterpret_cast<const int4*>(labels + b * TT);
        const int4 pa  = lb[tid * 2];
        const int4 pb4 = lb[tid * 2 + 1];
        int l[8] = {pa.x, pa.y, pa.z, pa.w, pb4.x, pb4.y, pb4.z, pb4.w};

        int cnt = 0;
        #pragma unroll
        for (int j = 0; j < 8; j++) cnt += (l[j] == Bi);

        int incl = cnt;
        #pragma unroll
        for (int o = 1; o < 32; o <<= 1) {
            const int u = __shfl_up_sync(0xFFFFFFFFu, incl, o);
            if (lane >= o) incl += u;
        }
        if (lane == 31) wsum[warp] = incl;
        __syncthreads();

        int base = 0;
        #pragma unroll
        for (int wv = 0; wv < 4; wv++) base += (wv < warp) ? wsum[wv] : 0;

        int run = base + incl - cnt;     // exclusive B-count before token tid*8
        #pragma unroll
        for (int j = 0; j < 8; j++) {
            const int isB = (l[j] == Bi);
            run += isB;
            const int span  = run - 1;
            const bool valid = (isB | (l[j] == Ii)) && span >= 0;
            const int tokg = tid * 8 + j;
            if ((unsigned)(tokg - tok0) < 64u)
                seg_sh[tokg - tok0] = valid ? span : -1;
        }
    }
    __syncthreads();

    // temp slice in registers: 8 float4 = 32 regs, read once from L2.
    float4 ta[KK];
    #pragma unroll
    for (int k = 0; k < KK; k++)
        ta[k] = *reinterpret_cast<const float4*>(
            g_temp + ((size_t)b * KK + k) * DD + d0);

    const float* hb = hidden + ((size_t)b * TT + tok0) * DD + d0;
    float* const ob = out + (size_t)b * TT * KK + (lane & 7);
    const int myt = lane >> 3;

    #pragma unroll 1
    for (int g = 0; g < 64; g += 4) {
        // 4 independent coalesced LDG.128 (evict-first: hidden read once).
        float4 h[4];
        #pragma unroll
        for (int t = 0; t < 4; t++)
            h[t] = __ldcs(reinterpret_cast<const float4*>(hb + (size_t)(g + t) * DD));

        float v[32];   // v[t*8+k] = this lane's 4-float partial dot
        #pragma unroll
        for (int k = 0; k < KK; k++) {
            #pragma unroll
            for (int t = 0; t < 4; t++) {
                float a;
                a = h[t].x * ta[k].x;
                a = fmaf(h[t].y, ta[k].y, a);
                a = fmaf(h[t].z, ta[k].z, a);
                a = fmaf(h[t].w, ta[k].w, a);
                v[t * 8 + k] = a;
            }
        }

        // Butterfly-halving all-reduce: 32 values x 32 lanes; the fully
        // reduced value index == lane after steps m=16..1.
        #pragma unroll
        for (int m = 16; m >= 1; m >>= 1) {
            const bool up = (lane & m) != 0;
            #pragma unroll
            for (int i = 0; i < m; i++) {
                float send = up ? v[i] : v[i + m];
                float recv = __shfl_xor_sync(0xFFFFFFFFu, send, m);
                v[i] = (up ? v[i + m] : v[i]) + recv;
            }
        }

        const int s = seg_sh[g + myt];
        if (s >= 0)
            atomicAdd(ob + (size_t)s * KK, v[0]);
    }
}

// ---------------------------------------------------------------------------
extern "C" void kernel_launch(void* const* d_in, const int* in_sizes, int n_in,
                              void* d_out, int out_size)
{
    const float* hidden = (const float*)d_in[0];   // [32,1024,1024] f32
    const float* slot   = (const float*)d_in[1];   // [32,400,8]     f32
    const float* W      = (const float*)d_in[2];   // [400,1024]     f32
    const int*   labels = (const int*)  d_in[3];   // [32,1024]      i32
    const int*   pB     = (n_in > 4) ? (const int*)d_in[4] : nullptr;
    const int*   pI     = (n_in > 5) ? (const int*)d_in[5] : nullptr;
    float* out = (float*)d_out;

    (void)in_sizes; (void)out_size;

    temp_partial_kernel<<<dim3(2, BZ / 2, ESPLIT), 128>>>(slot, W);
    temp_reduce_kernel <<<BZ * KK * DD / 4 / 256, 256>>>(out);
    main_kernel        <<<dim3(TT / 64, BZ, 2), 128>>>(hidden, labels, pB, pI, out);
}